// round 11
// baseline (speedup 1.0000x reference)
#include <cuda_runtime.h>
#include <cuda_bf16.h>
#include <cuda_fp16.h>
#include <math.h>
#include <stdint.h>

#define D_MODEL 1024
#define NHEAD   16
#define HDIM    64
#define T_SEQ   2048
#define BATCH   2
#define M_TOT   (BATCH*T_SEQ)   /* 4096 */
#define INT_DIM 4096

typedef __nv_bfloat16  bf16;
typedef __nv_bfloat162 bf162;

// ---------------- scratch (static device globals; no runtime allocation) ----
__device__ float g_tmp[(size_t)M_TOT*D_MODEL];
__device__ float g_h  [(size_t)M_TOT*D_MODEL];
__device__ half  g_qh [(size_t)M_TOT*D_MODEL];
__device__ half  g_kh [(size_t)M_TOT*D_MODEL];
__device__ half  g_vh [(size_t)M_TOT*D_MODEL];
__device__ bf16  g_xb [(size_t)M_TOT*D_MODEL];
__device__ bf16  g_atb[(size_t)M_TOT*D_MODEL];
__device__ half  g_hh [(size_t)M_TOT*D_MODEL];
__device__ half  g_ffh[(size_t)M_TOT*INT_DIM];
// transposed weights [N][K]; qkv concatenated along N
__device__ bf16 g_wqkvT[(size_t)3*D_MODEL*D_MODEL];
__device__ bf16 g_woT[(size_t)D_MODEL*D_MODEL];
__device__ half g_w1T[(size_t)INT_DIM*D_MODEL];
__device__ half g_w2T[(size_t)D_MODEL*INT_DIM];

// ================= helpers =================
__device__ __forceinline__ uint32_t smem_u32(const void* p) {
    uint32_t a;
    asm("{ .reg .u64 t; cvta.to.shared.u64 t, %1; cvt.u32.u64 %0, t; }" : "=r"(a) : "l"(p));
    return a;
}
__device__ __forceinline__ void cp16(uint32_t dst, const void* src) {
    asm volatile("cp.async.cg.shared.global [%0], [%1], 16;" :: "r"(dst), "l"(src));
}
#define CP_COMMIT() asm volatile("cp.async.commit_group;" ::: "memory")
#define CP_WAITN(n) asm volatile("cp.async.wait_group %0;" :: "n"(n) : "memory")

#define LDM_X4(d, addr) \
    asm volatile("ldmatrix.sync.aligned.m8n8.x4.shared.b16 {%0,%1,%2,%3}, [%4];" \
        : "=r"((d)[0]), "=r"((d)[1]), "=r"((d)[2]), "=r"((d)[3]) : "r"(addr))
#define LDM_X4T(d, addr) \
    asm volatile("ldmatrix.sync.aligned.m8n8.x4.trans.shared.b16 {%0,%1,%2,%3}, [%4];" \
        : "=r"((d)[0]), "=r"((d)[1]), "=r"((d)[2]), "=r"((d)[3]) : "r"(addr))
#define LDM_X2T(d, addr) \
    asm volatile("ldmatrix.sync.aligned.m8n8.x2.trans.shared.b16 {%0,%1}, [%2];" \
        : "=r"((d)[0]), "=r"((d)[1]) : "r"(addr))

#define MMA_BF16(c, a, b0, b1) \
    asm volatile("mma.sync.aligned.m16n8k16.row.col.f32.bf16.bf16.f32 " \
        "{%0,%1,%2,%3}, {%4,%5,%6,%7}, {%8,%9}, {%0,%1,%2,%3};" \
        : "+f"((c)[0]), "+f"((c)[1]), "+f"((c)[2]), "+f"((c)[3]) \
        : "r"((a)[0]), "r"((a)[1]), "r"((a)[2]), "r"((a)[3]), "r"(b0), "r"(b1))

#define MMA_F16(c, a, b0, b1) \
    asm volatile("mma.sync.aligned.m16n8k16.row.col.f32.f16.f16.f32 " \
        "{%0,%1,%2,%3}, {%4,%5,%6,%7}, {%8,%9}, {%0,%1,%2,%3};" \
        : "+f"((c)[0]), "+f"((c)[1]), "+f"((c)[2]), "+f"((c)[3]) \
        : "r"((a)[0]), "r"((a)[1]), "r"((a)[2]), "r"((a)[3]), "r"(b0), "r"(b1))

__device__ __forceinline__ uint32_t exp2_f16x2(float a, float b) {
    uint32_t d;
    asm("{ .reg .b32 t; cvt.rn.f16x2.f32 t, %1, %2; ex2.approx.f16x2 %0, t; }"
        : "=r"(d) : "f"(b), "f"(a));
    return d;
}

#define T_BYTES   18432                 /* 128 * 144 */
#define ST_BYTES  (2 * T_BYTES)
#define SMEM_G    (3 * ST_BYTES)        /* 110592 */

// ================= shared GEMM machinery (128 threads/CTA) =================
template<typename T>
__device__ __forceinline__ void load_stage2(
    uint32_t st, const T* A, const T* B, int K, int kb, int tid)
{
    const T* srcs[2] = {A, B};
#pragma unroll
    for (int i = 0; i < 16; i++) {
        const int t   = i >> 3;
        const int row = (tid >> 3) + (i & 7) * 16;
        const int j   = tid & 7;
        cp16(st + t * T_BYTES + row * 144 + j * 16,
             srcs[t] + (size_t)row * K + kb + j * 8);
    }
}

// mainloop: 4 warps, warp tile 64x64 (2x2 warp grid), CTA tile 128x128.
// Per k-step per warp: 4 A-ldmatrix + 4 B-ldmatrix -> 32 MMAs (ILP-dense).
#define GEMM_MAINLOOP(DT)                                                      \
    float acc[4][8][4];                                                        \
    _Pragma("unroll")                                                          \
    for (int i = 0; i < 4; i++)                                                \
        _Pragma("unroll")                                                      \
        for (int j = 0; j < 8; j++)                                            \
            _Pragma("unroll")                                                  \
            for (int t = 0; t < 4; t++) acc[i][j][t] = 0.f;                    \
    _Pragma("unroll")                                                          \
    for (int s = 0; s < 3; s++) {                                              \
        load_stage2(sb + s * ST_BYTES, aB, bB, K, s * 64, tid);                \
        CP_COMMIT();                                                           \
    }                                                                          \
    const int r = lane & 7;                                                    \
    const int aRow = r + ((lane >> 3) & 1) * 8;                                \
    const int aK16 = ((lane >> 4) & 1) * 16;                                   \
    const int bRow = r + ((lane >> 4) & 1) * 8;                                \
    const int bK16 = ((lane >> 3) & 1) * 16;                                   \
    for (int c = 0; c < NC; c++) {                                             \
        const int s = c - (c / 3) * 3;                                         \
        const uint32_t st = sb + s * ST_BYTES;                                 \
        CP_WAITN(2);                                                           \
        __syncthreads();                                                       \
        const uint32_t aA = st + (mbase + aRow) * 144 + aK16;                  \
        const uint32_t bA = st + T_BYTES + (nbase + bRow) * 144 + bK16;        \
        _Pragma("unroll")                                                      \
        for (int ks = 0; ks < 4; ks++) {                                       \
            uint32_t a[4][4], b[4][4];                                         \
            _Pragma("unroll")                                                  \
            for (int mf = 0; mf < 4; mf++) LDM_X4(a[mf], aA + mf * 2304 + ks * 32); \
            _Pragma("unroll")                                                  \
            for (int p = 0; p < 4; p++)   LDM_X4(b[p], bA + p * 2304 + ks * 32);    \
            _Pragma("unroll")                                                  \
            for (int mf = 0; mf < 4; mf++)                                     \
                _Pragma("unroll")                                              \
                for (int nf = 0; nf < 8; nf++) {                               \
                    const int p = nf >> 1, q = (nf & 1) * 2;                   \
                    if (DT == 0) MMA_BF16(acc[mf][nf], a[mf], b[p][q], b[p][q + 1]); \
                    else         MMA_F16 (acc[mf][nf], a[mf], b[p][q], b[p][q + 1]); \
                }                                                              \
        }                                                                      \
        __syncthreads();                                                       \
        if (c + 3 < NC)                                                        \
            load_stage2(st, aB, bB, K, (c + 3) * 64, tid);                     \
        CP_COMMIT();                                                           \
    }

// ---------------- generic GEMM: EPI 0 fp32 out, 1 relu + fp16 out ----------
template<int DT, int EPI, typename T>
__global__ __launch_bounds__(128)
void gemm16(const T* __restrict__ A, const T* __restrict__ Bt,
            const float* __restrict__ bias,
            float* __restrict__ C, half* __restrict__ Ch,
            int M, int N, int K)
{
    extern __shared__ __align__(256) char smem[];
    const uint32_t sb = smem_u32(smem);
    const int tid = threadIdx.x;
    const int lane = tid & 31, wid = tid >> 5;
    const int warp_m = wid & 1, warp_n = wid >> 1;
    const int mbase = warp_m * 64, nbase = warp_n * 64;
    const int bm = blockIdx.y * 128, bn = blockIdx.x * 128;
    const int NC = K >> 6;
    const T* aB = A  + (size_t)bm * K;
    const T* bB = Bt + (size_t)bn * K;

    GEMM_MAINLOOP(DT)

    const int gid = lane >> 2, tg = lane & 3;
#pragma unroll
    for (int mf = 0; mf < 4; mf++)
#pragma unroll
        for (int nf = 0; nf < 8; nf++) {
            const int n = bn + nbase + nf * 8 + tg * 2;
            const float b0 = bias[n], b1 = bias[n + 1];
#pragma unroll
            for (int half_ = 0; half_ < 2; half_++) {
                const int m = bm + mbase + mf * 16 + gid + half_ * 8;
                float v0 = acc[mf][nf][half_ * 2 + 0] + b0;
                float v1 = acc[mf][nf][half_ * 2 + 1] + b1;
                if (EPI == 1) {
                    v0 = fmaxf(v0, 0.f); v1 = fmaxf(v1, 0.f);
                    *(half2*)&Ch[(size_t)m * N + n] = __floats2half2_rn(v0, v1);
                } else {
                    *(float2*)&C[(size_t)m * N + n] = make_float2(v0, v1);
                }
            }
        }
}

// ---------------- fused QKV GEMM: N = 3072, writes q/k/v fp16 [B,H,T,64] ----
__global__ __launch_bounds__(128)
void gemm_qkv(const bf16* __restrict__ A, const bf16* __restrict__ Bt,
              const float* __restrict__ bq, const float* __restrict__ bk,
              const float* __restrict__ bv,
              half* __restrict__ Qh, half* __restrict__ Kh, half* __restrict__ Vh,
              int M, int K)
{
    extern __shared__ __align__(256) char smem[];
    const uint32_t sb = smem_u32(smem);
    const int tid = threadIdx.x;
    const int lane = tid & 31, wid = tid >> 5;
    const int warp_m = wid & 1, warp_n = wid >> 1;
    const int mbase = warp_m * 64, nbase = warp_n * 64;
    const int bm = blockIdx.y * 128, bn = blockIdx.x * 128;
    const int NC = K >> 6;
    const bf16* aB = A  + (size_t)bm * K;
    const bf16* bB = Bt + (size_t)bn * K;

    GEMM_MAINLOOP(0)

    const int gid = lane >> 2, tg = lane & 3;
#pragma unroll
    for (int mf = 0; mf < 4; mf++)
#pragma unroll
        for (int nf = 0; nf < 8; nf++) {
            const int n = bn + nbase + nf * 8 + tg * 2;     // 0..3071
            const int proj = n >> 10;                        // 0=q 1=k 2=v
            const int col  = n & 1023;
            const float* bias = (proj == 0) ? bq : (proj == 1) ? bk : bv;
            half* dst = (proj == 0) ? Qh : (proj == 1) ? Kh : Vh;
            const float b0 = bias[col], b1 = bias[col + 1];
            const int hh = col >> 6, d = col & 63;
#pragma unroll
            for (int half_ = 0; half_ < 2; half_++) {
                const int m = bm + mbase + mf * 16 + gid + half_ * 8;
                float v0 = acc[mf][nf][half_ * 2 + 0] + b0;
                float v1 = acc[mf][nf][half_ * 2 + 1] + b1;
                const int b = m >> 11, t = m & 2047;
                const size_t o = ((((size_t)b * NHEAD + hh) * T_SEQ) + t) * HDIM + d;
                *(half2*)&dst[o] = __floats2half2_rn(v0, v1);
            }
        }
}

// ================= fused pre-pass: x->bf16 + all weight transposes ==========
#define PREP_BLOCKS 16384
__global__ __launch_bounds__(256) void prep_kernel(
    const float* __restrict__ x,
    const float* __restrict__ Wq, const float* __restrict__ Wk,
    const float* __restrict__ Wv, const float* __restrict__ Wo,
    const float* __restrict__ W1, const float* __restrict__ W2)
{
    __shared__ float t[32][33];
    const int tid = threadIdx.x;
    int b = blockIdx.x;

    if (b < 4096) {          // x -> bf16
        const size_t i = ((size_t)b * 256 + tid) * 4;
        float4 v = *(const float4*)(x + i);
        *(bf162*)&g_xb[i]     = bf162(__float2bfloat16_rn(v.x), __float2bfloat16_rn(v.y));
        *(bf162*)&g_xb[i + 2] = bf162(__float2bfloat16_rn(v.z), __float2bfloat16_rn(v.w));
        return;
    }
    b -= 4096;

    const float* in;
    bf16* outb = nullptr;
    half* outh = nullptr;
    int R, Cc;
    if (b < 4096) {
        const int wsel = b >> 10;
        b &= 1023;
        in = (wsel == 0) ? Wq : (wsel == 1) ? Wk : (wsel == 2) ? Wv : Wo;
        outb = (wsel == 3) ? g_woT : g_wqkvT + (size_t)wsel * D_MODEL * D_MODEL;
        R = D_MODEL; Cc = D_MODEL;
    } else if (b < 8192) {
        b -= 4096;
        in = W1; outh = g_w1T; R = D_MODEL; Cc = INT_DIM;
    } else {
        b -= 8192;
        in = W2; outh = g_w2T; R = INT_DIM; Cc = D_MODEL;
    }

    const int nTx = Cc >> 5;
    const int bx = b % nTx, by = b / nTx;
    const int c0 = bx * 32, r0 = by * 32;
    const int xl = tid & 31, y = (tid >> 5) * 4;
#pragma unroll
    for (int i = 0; i < 4; i++)
        t[y + i][xl] = in[(size_t)(r0 + y + i) * Cc + c0 + xl];
    __syncthreads();
    if (outb) {
#pragma unroll
        for (int i = 0; i < 4; i++)
            outb[(size_t)(c0 + y + i) * R + r0 + xl] = __float2bfloat16_rn(t[xl][y + i]);
    } else {
#pragma unroll
        for (int i = 0; i < 4; i++)
            outh[(size_t)(c0 + y + i) * R + r0 + xl] = __float2half_rn(t[xl][y + i]);
    }
}

// ================= Flash attention (BLOCK_M=64, 128 thr) =====================
#define FA_STRIDE 144   /* 72 halves per row */
__global__ __launch_bounds__(128) void flash_mma()
{
    __shared__ half Qs[64 * 72];
    __shared__ half Ks[2][64 * 72];
    __shared__ half Vs[2][64 * 72];

    const int tid = threadIdx.x;
    const int lane = tid & 31, wid = tid >> 5;
    const int qb = blockIdx.x * 64;
    const int bh = blockIdx.y;
    const int mbase = wid * 16;

    const half* qp = g_qh + (size_t)bh * T_SEQ * HDIM;
    const half* kp = g_kh + (size_t)bh * T_SEQ * HDIM;
    const half* vp = g_vh + (size_t)bh * T_SEQ * HDIM;

    const uint32_t qbase = smem_u32(Qs);
    const uint32_t kbase = smem_u32(Ks);
    const uint32_t vbase = smem_u32(Vs);

#pragma unroll
    for (int t = 0; t < 8; t++) {
        int u = tid + t * 128;
        int buf = u >> 9, rem = u & 511;
        int row = rem >> 3, c = rem & 7;
        Vs[buf][row * 72 + 64 + c] = (c == 0) ? __float2half(1.0f) : __float2half(0.0f);
    }

#pragma unroll
    for (int t = 0; t < 4; t++) {
        int u = tid + t * 128;
        int row = u >> 3, j = u & 7;
        cp16(qbase + row * FA_STRIDE + j * 16, qp + (size_t)(qb + row) * 64 + j * 8);
        cp16(kbase + row * FA_STRIDE + j * 16, kp + (size_t)row * 64 + j * 8);
        cp16(vbase + row * FA_STRIDE + j * 16, vp + (size_t)row * 64 + j * 8);
    }
    CP_COMMIT();

    const int r = lane & 7;
    const int aRow = r + ((lane >> 3) & 1) * 8;
    const int aK16 = ((lane >> 4) & 1) * 16;
    const int bRow = r + ((lane >> 4) & 1) * 8;
    const int bK16 = ((lane >> 3) & 1) * 16;
    const int vRow = lane & 15;
    const int vCol = ((lane >> 4) & 1) * 8;

    float oacc[9][4];
#pragma unroll
    for (int i = 0; i < 9; i++)
#pragma unroll
        for (int j = 0; j < 4; j++) oacc[i][j] = 0.f;

    uint32_t qf[4][4];
    bool qloaded = false;
    const float CEXP = 0.1803368801f;   // log2(e)/8

    const int NIT = T_SEQ / 64;
    for (int it = 0; it < NIT; it++) {
        const int buf = it & 1;
        if (it + 1 < NIT) {
            const int nb = (it + 1) & 1;
            const half* kq = kp + (size_t)(it + 1) * 64 * 64;
            const half* vq = vp + (size_t)(it + 1) * 64 * 64;
#pragma unroll
            for (int t = 0; t < 4; t++) {
                int u = tid + t * 128;
                int row = u >> 3, j = u & 7;
                cp16(kbase + nb * 9216 + row * FA_STRIDE + j * 16, kq + (size_t)row * 64 + j * 8);
                cp16(vbase + nb * 9216 + row * FA_STRIDE + j * 16, vq + (size_t)row * 64 + j * 8);
            }
            CP_COMMIT();
            CP_WAITN(1);
        } else {
            CP_WAITN(0);
        }
        __syncthreads();

        if (!qloaded) {
            const uint32_t qa = qbase + (mbase + aRow) * FA_STRIDE + aK16;
#pragma unroll
            for (int ks = 0; ks < 4; ks++) LDM_X4(qf[ks], qa + ks * 32);
            qloaded = true;
        }

        float sacc[8][4];
#pragma unroll
        for (int i = 0; i < 8; i++)
#pragma unroll
            for (int j = 0; j < 4; j++) sacc[i][j] = 0.f;

        const uint32_t ka = kbase + buf * 9216 + bRow * FA_STRIDE + bK16;
#pragma unroll
        for (int ks = 0; ks < 4; ks++) {
            uint32_t kf[4][4];
#pragma unroll
            for (int p = 0; p < 4; p++) LDM_X4(kf[p], ka + p * 16 * FA_STRIDE + ks * 32);
#pragma unroll
            for (int nf = 0; nf < 8; nf++) {
                const int p = nf >> 1, q = (nf & 1) * 2;
                MMA_F16(sacc[nf], qf[ks], kf[p][q], kf[p][q + 1]);
            }
        }

        uint32_t pf[4][4];
#pragma unroll
        for (int t = 0; t < 4; t++) {
#pragma unroll
            for (int u = 0; u < 2; u++) {
                const int j = 2 * t + u;
                pf[t][u * 2 + 0] = exp2_f16x2(sacc[j][0] * CEXP, sacc[j][1] * CEXP);
                pf[t][u * 2 + 1] = exp2_f16x2(sacc[j][2] * CEXP, sacc[j][3] * CEXP);
            }
        }

        const uint32_t va = vbase + buf * 9216;
#pragma unroll
        for (int t = 0; t < 4; t++) {
            const uint32_t vrow = va + (t * 16 + vRow) * FA_STRIDE;
            uint32_t vf[4][4], vf8[2];
#pragma unroll
            for (int p = 0; p < 4; p++) LDM_X4T(vf[p], vrow + (p * 16 + vCol) * 2);
            LDM_X2T(vf8, vrow + 64 * 2);
#pragma unroll
            for (int nf = 0; nf < 8; nf++) {
                const int p = nf >> 1, q = (nf & 1) * 2;
                MMA_F16(oacc[nf], pf[t], vf[p][q], vf[p][q + 1]);
            }
            MMA_F16(oacc[8], pf[t], vf8[0], vf8[1]);
        }
        __syncthreads();
    }

    const int gid = lane >> 2, tg = lane & 3;
    const float l0 = __shfl_sync(0xffffffffu, oacc[8][0], lane & ~3);
    const float l1 = __shfl_sync(0xffffffffu, oacc[8][2], lane & ~3);
    const float inv0 = 1.f / l0, inv1 = 1.f / l1;

    const int b = bh >> 4, h = bh & 15;
    const size_t row0 = (size_t)(b * T_SEQ + qb + mbase + gid);
#pragma unroll
    for (int nf = 0; nf < 8; nf++) {
        const int col = h * 64 + nf * 8 + tg * 2;
        *(bf162*)&g_atb[row0 * D_MODEL + col] =
            bf162(__float2bfloat16_rn(oacc[nf][0] * inv0),
                  __float2bfloat16_rn(oacc[nf][1] * inv0));
        *(bf162*)&g_atb[(row0 + 8) * D_MODEL + col] =
            bf162(__float2bfloat16_rn(oacc[nf][2] * inv1),
                  __float2bfloat16_rn(oacc[nf][3] * inv1));
    }
}

// ================= residual + LayerNorm (optional fp16 copy) =================
template<int HOUT>
__global__ __launch_bounds__(256) void ln_kernel(
    const float* __restrict__ A, const float* __restrict__ Cv,
    const float* __restrict__ gamma, const float* __restrict__ beta,
    float* __restrict__ out, half* __restrict__ outh)
{
    __shared__ float red[18];
    const int row = blockIdx.x;
    const int tid = threadIdx.x;
    const int lane = tid & 31, wid = tid >> 5;

    float4 av = ((const float4*)(A  + (size_t)row * D_MODEL))[tid];
    float4 cv = ((const float4*)(Cv + (size_t)row * D_MODEL))[tid];
    float4 s = make_float4(av.x + cv.x, av.y + cv.y, av.z + cv.z, av.w + cv.w);

    float sum = s.x + s.y + s.z + s.w;
    float sq  = s.x * s.x + s.y * s.y + s.z * s.z + s.w * s.w;
#pragma unroll
    for (int off = 16; off; off >>= 1) {
        sum += __shfl_xor_sync(0xffffffffu, sum, off);
        sq  += __shfl_xor_sync(0xffffffffu, sq, off);
    }
    if (lane == 0) { red[wid] = sum; red[wid + 8] = sq; }
    __syncthreads();
    if (tid == 0) {
        float ts = 0.f, tq = 0.f;
        for (int i = 0; i < 8; i++) { ts += red[i]; tq += red[i + 8]; }
        red[16] = ts; red[17] = tq;
    }
    __syncthreads();

    float mean = red[16] * (1.f / 1024.f);
    float var  = red[17] * (1.f / 1024.f) - mean * mean;
    float rstd = rsqrtf(var + 1e-5f);

    float4 g4 = ((const float4*)gamma)[tid];
    float4 b4 = ((const float4*)beta)[tid];
    float4 rr;
    rr.x = (s.x - mean) * rstd * g4.x + b4.x;
    rr.y = (s.y - mean) * rstd * g4.y + b4.y;
    rr.z = (s.z - mean) * rstd * g4.z + b4.z;
    rr.w = (s.w - mean) * rstd * g4.w + b4.w;
    ((float4*)(out + (size_t)row * D_MODEL))[tid] = rr;

    if (HOUT) {
        size_t base = (size_t)row * D_MODEL + tid * 4;
        *(half2*)&outh[base]     = __floats2half2_rn(rr.x, rr.y);
        *(half2*)&outh[base + 2] = __floats2half2_rn(rr.z, rr.w);
    }
}

// ================= launch =================
extern "C" void kernel_launch(void* const* d_in, const int* in_sizes, int n_in,
                              void* d_out, int out_size)
{
    const float* x     = (const float*)d_in[0];
    const float* Wq    = (const float*)d_in[1];
    const float* bq    = (const float*)d_in[2];
    const float* Wk    = (const float*)d_in[3];
    const float* bk    = (const float*)d_in[4];
    const float* Wv    = (const float*)d_in[5];
    const float* bv    = (const float*)d_in[6];
    const float* Wo    = (const float*)d_in[7];
    const float* bo    = (const float*)d_in[8];
    const float* ln1_g = (const float*)d_in[9];
    const float* ln1_b = (const float*)d_in[10];
    const float* ln2_g = (const float*)d_in[11];
    const float* ln2_b = (const float*)d_in[12];
    const float* W1    = (const float*)d_in[13];
    const float* b1    = (const float*)d_in[14];
    const float* W2    = (const float*)d_in[15];
    const float* b2    = (const float*)d_in[16];

    float *tmp, *h;
    half *qh, *kh, *vh, *hh, *ffh, *w1T, *w2T;
    bf16 *xb, *atb, *wqkvT, *woT;
    cudaGetSymbolAddress((void**)&tmp,   g_tmp);
    cudaGetSymbolAddress((void**)&h,     g_h);
    cudaGetSymbolAddress((void**)&qh,    g_qh);
    cudaGetSymbolAddress((void**)&kh,    g_kh);
    cudaGetSymbolAddress((void**)&vh,    g_vh);
    cudaGetSymbolAddress((void**)&xb,    g_xb);
    cudaGetSymbolAddress((void**)&atb,   g_atb);
    cudaGetSymbolAddress((void**)&hh,    g_hh);
    cudaGetSymbolAddress((void**)&ffh,   g_ffh);
    cudaGetSymbolAddress((void**)&wqkvT, g_wqkvT);
    cudaGetSymbolAddress((void**)&woT,   g_woT);
    cudaGetSymbolAddress((void**)&w1T,   g_w1T);
    cudaGetSymbolAddress((void**)&w2T,   g_w2T);

    cudaFuncSetAttribute((const void*)gemm16<0, 0, bf16>, cudaFuncAttributeMaxDynamicSharedMemorySize, SMEM_G);
    cudaFuncSetAttribute((const void*)gemm16<1, 0, half>, cudaFuncAttributeMaxDynamicSharedMemorySize, SMEM_G);
    cudaFuncSetAttribute((const void*)gemm16<1, 1, half>, cudaFuncAttributeMaxDynamicSharedMemorySize, SMEM_G);
    cudaFuncSetAttribute((const void*)gemm_qkv, cudaFuncAttributeMaxDynamicSharedMemorySize, SMEM_G);

    dim3 blk256(256);
    dim3 blk128(128);

    // single fused pre-pass
    prep_kernel<<<PREP_BLOCKS, blk256>>>(x, Wq, Wk, Wv, Wo, W1, W2);

    dim3 gD(D_MODEL/128, M_TOT/128);       // (8, 32)
    dim3 gQKV(3*D_MODEL/128, M_TOT/128);   // (24, 32)
    dim3 gF(INT_DIM/128, M_TOT/128);       // (32, 32)

    // fused Q/K/V projection (bf16) -> fp16 [B,H,T,64]
    gemm_qkv<<<gQKV, blk128, SMEM_G>>>(xb, wqkvT, bq, bk, bv, qh, kh, vh, M_TOT, D_MODEL);

    // attention (fp16 HMMA, 64-query tiles, 128 threads) -> atb bf16 [B,T,D]
    flash_mma<<<dim3(T_SEQ/64, BATCH*NHEAD), blk128>>>();

    // output projection (bf16) -> tmp fp32
    gemm16<0, 0, bf16><<<gD, blk128, SMEM_G>>>(atb, woT, bo, tmp, nullptr, M_TOT, D_MODEL, D_MODEL);

    // h = LN(x + attn_out), fp16 copy for FFN
    ln_kernel<1><<<M_TOT, blk256>>>(x, tmp, ln1_g, ln1_b, h, hh);

    // FFN: plain fp16, f32 accum
    gemm16<1, 1, half><<<gF, blk128, SMEM_G>>>(hh, w1T, b1, nullptr, ffh, M_TOT, INT_DIM, D_MODEL);
    gemm16<1, 0, half><<<gD, blk128, SMEM_G>>>(ffh, w2T, b2, tmp, nullptr, M_TOT, D_MODEL, INT_DIM);

    // out = LN(h + ffn_out)
    ln_kernel<0><<<M_TOT, blk256>>>(h, tmp, ln2_g, ln2_b, (float*)d_out, nullptr);
}

// round 12
// speedup vs baseline: 1.0279x; 1.0279x over previous
#include <cuda_runtime.h>
#include <cuda_bf16.h>
#include <cuda_fp16.h>
#include <math.h>
#include <stdint.h>

#define D_MODEL 1024
#define NHEAD   16
#define HDIM    64
#define T_SEQ   2048
#define BATCH   2
#define M_TOT   (BATCH*T_SEQ)   /* 4096 */
#define INT_DIM 4096

typedef __nv_bfloat16  bf16;
typedef __nv_bfloat162 bf162;

// ---------------- scratch (static device globals; no runtime allocation) ----
__device__ float g_tmp[(size_t)M_TOT*D_MODEL];
__device__ float g_h  [(size_t)M_TOT*D_MODEL];
__device__ half  g_qh [(size_t)M_TOT*D_MODEL];
__device__ half  g_kh [(size_t)M_TOT*D_MODEL];
__device__ half  g_vh [(size_t)M_TOT*D_MODEL];
__device__ bf16  g_xb [(size_t)M_TOT*D_MODEL];
__device__ bf16  g_atb[(size_t)M_TOT*D_MODEL];
__device__ half  g_hh [(size_t)M_TOT*D_MODEL];
__device__ half  g_ffh[(size_t)M_TOT*INT_DIM];
// transposed weights [N][K]; qkv concatenated along N
__device__ bf16 g_wqkvT[(size_t)3*D_MODEL*D_MODEL];
__device__ bf16 g_woT[(size_t)D_MODEL*D_MODEL];
__device__ half g_w1T[(size_t)INT_DIM*D_MODEL];
__device__ half g_w2T[(size_t)D_MODEL*INT_DIM];

// ================= helpers =================
__device__ __forceinline__ uint32_t smem_u32(const void* p) {
    uint32_t a;
    asm("{ .reg .u64 t; cvta.to.shared.u64 t, %1; cvt.u32.u64 %0, t; }" : "=r"(a) : "l"(p));
    return a;
}
__device__ __forceinline__ void cp16(uint32_t dst, const void* src) {
    asm volatile("cp.async.cg.shared.global [%0], [%1], 16;" :: "r"(dst), "l"(src));
}
#define CP_COMMIT() asm volatile("cp.async.commit_group;" ::: "memory")
#define CP_WAITN(n) asm volatile("cp.async.wait_group %0;" :: "n"(n) : "memory")

#define LDM_X4(d, addr) \
    asm volatile("ldmatrix.sync.aligned.m8n8.x4.shared.b16 {%0,%1,%2,%3}, [%4];" \
        : "=r"((d)[0]), "=r"((d)[1]), "=r"((d)[2]), "=r"((d)[3]) : "r"(addr))
#define LDM_X4T(d, addr) \
    asm volatile("ldmatrix.sync.aligned.m8n8.x4.trans.shared.b16 {%0,%1,%2,%3}, [%4];" \
        : "=r"((d)[0]), "=r"((d)[1]), "=r"((d)[2]), "=r"((d)[3]) : "r"(addr))
#define LDM_X2T(d, addr) \
    asm volatile("ldmatrix.sync.aligned.m8n8.x2.trans.shared.b16 {%0,%1}, [%2];" \
        : "=r"((d)[0]), "=r"((d)[1]) : "r"(addr))

#define MMA_BF16(c, a, b0, b1) \
    asm volatile("mma.sync.aligned.m16n8k16.row.col.f32.bf16.bf16.f32 " \
        "{%0,%1,%2,%3}, {%4,%5,%6,%7}, {%8,%9}, {%0,%1,%2,%3};" \
        : "+f"((c)[0]), "+f"((c)[1]), "+f"((c)[2]), "+f"((c)[3]) \
        : "r"((a)[0]), "r"((a)[1]), "r"((a)[2]), "r"((a)[3]), "r"(b0), "r"(b1))

#define MMA_F16(c, a, b0, b1) \
    asm volatile("mma.sync.aligned.m16n8k16.row.col.f32.f16.f16.f32 " \
        "{%0,%1,%2,%3}, {%4,%5,%6,%7}, {%8,%9}, {%0,%1,%2,%3};" \
        : "+f"((c)[0]), "+f"((c)[1]), "+f"((c)[2]), "+f"((c)[3]) \
        : "r"((a)[0]), "r"((a)[1]), "r"((a)[2]), "r"((a)[3]), "r"(b0), "r"(b1))

__device__ __forceinline__ uint32_t exp2_f16x2(float a, float b) {
    uint32_t d;
    asm("{ .reg .b32 t; cvt.rn.f16x2.f32 t, %1, %2; ex2.approx.f16x2 %0, t; }"
        : "=r"(d) : "f"(b), "f"(a));
    return d;
}

#define T_BYTES   18432                 /* 128 * 144 */
#define ST_BYTES  (2 * T_BYTES)
#define SMEM_G    (3 * ST_BYTES)        /* 110592 */

// ================= shared GEMM machinery (R8 config: 256 thr, 64x32 warps) ==
template<typename T>
__device__ __forceinline__ void load_stage2(
    uint32_t st, const T* A, const T* B, int K, int kb, int tid)
{
    const T* srcs[2] = {A, B};
#pragma unroll
    for (int i = 0; i < 8; i++) {
        const int t   = i >> 2;
        const int row = (tid >> 3) + (i & 3) * 32;
        const int j   = tid & 7;
        cp16(st + t * T_BYTES + row * 144 + j * 16,
             srcs[t] + (size_t)row * K + kb + j * 8);
    }
}

#define GEMM_MAINLOOP(DT)                                                      \
    float acc[4][4][4];                                                        \
    _Pragma("unroll")                                                          \
    for (int i = 0; i < 4; i++)                                                \
        _Pragma("unroll")                                                      \
        for (int j = 0; j < 4; j++)                                            \
            _Pragma("unroll")                                                  \
            for (int t = 0; t < 4; t++) acc[i][j][t] = 0.f;                    \
    _Pragma("unroll")                                                          \
    for (int s = 0; s < 3; s++) {                                              \
        load_stage2(sb + s * ST_BYTES, aB, bB, K, s * 64, tid);                \
        CP_COMMIT();                                                           \
    }                                                                          \
    const int r = lane & 7;                                                    \
    const int aRow = r + ((lane >> 3) & 1) * 8;                                \
    const int aK16 = ((lane >> 4) & 1) * 16;                                   \
    const int bRow = r + ((lane >> 4) & 1) * 8;                                \
    const int bK16 = ((lane >> 3) & 1) * 16;                                   \
    for (int c = 0; c < NC; c++) {                                             \
        const int s = c - (c / 3) * 3;                                         \
        const uint32_t st = sb + s * ST_BYTES;                                 \
        CP_WAITN(2);                                                           \
        __syncthreads();                                                       \
        const uint32_t aA = st + (mbase + aRow) * 144 + aK16;                  \
        const uint32_t bA = st + T_BYTES + (nbase + bRow) * 144 + bK16;        \
        _Pragma("unroll")                                                      \
        for (int ks = 0; ks < 4; ks++) {                                       \
            uint32_t a[4][4], b[2][4];                                         \
            _Pragma("unroll")                                                  \
            for (int mf = 0; mf < 4; mf++) LDM_X4(a[mf], aA + mf * 2304 + ks * 32); \
            _Pragma("unroll")                                                  \
            for (int p = 0; p < 2; p++)   LDM_X4(b[p], bA + p * 2304 + ks * 32);    \
            _Pragma("unroll")                                                  \
            for (int mf = 0; mf < 4; mf++)                                     \
                _Pragma("unroll")                                              \
                for (int nf = 0; nf < 4; nf++) {                               \
                    const int p = nf >> 1, q = (nf & 1) * 2;                   \
                    if (DT == 0) MMA_BF16(acc[mf][nf], a[mf], b[p][q], b[p][q + 1]); \
                    else         MMA_F16 (acc[mf][nf], a[mf], b[p][q], b[p][q + 1]); \
                }                                                              \
        }                                                                      \
        __syncthreads();                                                       \
        if (c + 3 < NC)                                                        \
            load_stage2(st, aB, bB, K, (c + 3) * 64, tid);                     \
        CP_COMMIT();                                                           \
    }

// ---------------- generic GEMM: EPI 0 fp32 out, 1 relu + fp16 out ----------
template<int DT, int EPI, typename T>
__global__ __launch_bounds__(256)
void gemm16(const T* __restrict__ A, const T* __restrict__ Bt,
            const float* __restrict__ bias,
            float* __restrict__ C, half* __restrict__ Ch,
            int M, int N, int K)
{
    extern __shared__ __align__(256) char smem[];
    const uint32_t sb = smem_u32(smem);
    const int tid = threadIdx.x;
    const int lane = tid & 31, wid = tid >> 5;
    const int warp_m = wid & 1, warp_n = wid >> 1;
    const int mbase = warp_m * 64, nbase = warp_n * 32;
    const int bm = blockIdx.y * 128, bn = blockIdx.x * 128;
    const int NC = K >> 6;
    const T* aB = A  + (size_t)bm * K;
    const T* bB = Bt + (size_t)bn * K;

    GEMM_MAINLOOP(DT)

    const int gid = lane >> 2, tg = lane & 3;
#pragma unroll
    for (int mf = 0; mf < 4; mf++)
#pragma unroll
        for (int nf = 0; nf < 4; nf++) {
            const int n = bn + nbase + nf * 8 + tg * 2;
            const float b0 = bias[n], b1 = bias[n + 1];
#pragma unroll
            for (int half_ = 0; half_ < 2; half_++) {
                const int m = bm + mbase + mf * 16 + gid + half_ * 8;
                float v0 = acc[mf][nf][half_ * 2 + 0] + b0;
                float v1 = acc[mf][nf][half_ * 2 + 1] + b1;
                if (EPI == 1) {
                    v0 = fmaxf(v0, 0.f); v1 = fmaxf(v1, 0.f);
                    *(half2*)&Ch[(size_t)m * N + n] = __floats2half2_rn(v0, v1);
                } else {
                    *(float2*)&C[(size_t)m * N + n] = make_float2(v0, v1);
                }
            }
        }
}

// ---------------- fused QKV GEMM: N = 3072, writes q/k/v fp16 [B,H,T,64] ----
__global__ __launch_bounds__(256)
void gemm_qkv(const bf16* __restrict__ A, const bf16* __restrict__ Bt,
              const float* __restrict__ bq, const float* __restrict__ bk,
              const float* __restrict__ bv,
              half* __restrict__ Qh, half* __restrict__ Kh, half* __restrict__ Vh,
              int M, int K)
{
    extern __shared__ __align__(256) char smem[];
    const uint32_t sb = smem_u32(smem);
    const int tid = threadIdx.x;
    const int lane = tid & 31, wid = tid >> 5;
    const int warp_m = wid & 1, warp_n = wid >> 1;
    const int mbase = warp_m * 64, nbase = warp_n * 32;
    const int bm = blockIdx.y * 128, bn = blockIdx.x * 128;
    const int NC = K >> 6;
    const bf16* aB = A  + (size_t)bm * K;
    const bf16* bB = Bt + (size_t)bn * K;

    GEMM_MAINLOOP(0)

    const int gid = lane >> 2, tg = lane & 3;
#pragma unroll
    for (int mf = 0; mf < 4; mf++)
#pragma unroll
        for (int nf = 0; nf < 4; nf++) {
            const int n = bn + nbase + nf * 8 + tg * 2;     // 0..3071
            const int proj = n >> 10;                        // 0=q 1=k 2=v
            const int col  = n & 1023;
            const float* bias = (proj == 0) ? bq : (proj == 1) ? bk : bv;
            half* dst = (proj == 0) ? Qh : (proj == 1) ? Kh : Vh;
            const float b0 = bias[col], b1 = bias[col + 1];
            const int hh = col >> 6, d = col & 63;
#pragma unroll
            for (int half_ = 0; half_ < 2; half_++) {
                const int m = bm + mbase + mf * 16 + gid + half_ * 8;
                float v0 = acc[mf][nf][half_ * 2 + 0] + b0;
                float v1 = acc[mf][nf][half_ * 2 + 1] + b1;
                const int b = m >> 11, t = m & 2047;
                const size_t o = ((((size_t)b * NHEAD + hh) * T_SEQ) + t) * HDIM + d;
                *(half2*)&dst[o] = __floats2half2_rn(v0, v1);
            }
        }
}

// ================= fused pre-pass (coalesced transposes) =====================
// Transpose tiles are 64 input-rows x 32 input-cols; output writes are full
// 128-byte lines (64 consecutive 16-bit values via paired stores).
// region map (blockIdx.x):
//   [0, 4096)        cvt x -> g_xb
//   [4096, 6144)     Wq/Wk/Wv/Wo -> bf16 transposes (512 blocks each)
//   [6144, 8192)     W1 [1024][4096] -> g_w1T (fp16)
//   [8192, 10240)    W2 [4096][1024] -> g_w2T (fp16)
#define PREP_BLOCKS 10240
__global__ __launch_bounds__(256) void prep_kernel(
    const float* __restrict__ x,
    const float* __restrict__ Wq, const float* __restrict__ Wk,
    const float* __restrict__ Wv, const float* __restrict__ Wo,
    const float* __restrict__ W1, const float* __restrict__ W2)
{
    __shared__ float t[64][33];
    const int tid = threadIdx.x;
    int b = blockIdx.x;

    if (b < 4096) {          // x -> bf16
        const size_t i = ((size_t)b * 256 + tid) * 4;
        float4 v = *(const float4*)(x + i);
        *(bf162*)&g_xb[i]     = bf162(__float2bfloat16_rn(v.x), __float2bfloat16_rn(v.y));
        *(bf162*)&g_xb[i + 2] = bf162(__float2bfloat16_rn(v.z), __float2bfloat16_rn(v.w));
        return;
    }
    b -= 4096;

    const float* in;
    bf16* outb = nullptr;
    half* outh = nullptr;
    int R, Cc;
    if (b < 2048) {          // four 1024x1024 bf16 transposes, 512 blocks each
        const int wsel = b >> 9;
        b &= 511;
        in = (wsel == 0) ? Wq : (wsel == 1) ? Wk : (wsel == 2) ? Wv : Wo;
        outb = (wsel == 3) ? g_woT : g_wqkvT + (size_t)wsel * D_MODEL * D_MODEL;
        R = D_MODEL; Cc = D_MODEL;
    } else if (b < 4096) {   // W1
        b -= 2048;
        in = W1; outh = g_w1T; R = D_MODEL; Cc = INT_DIM;
    } else {                 // W2
        b -= 4096;
        in = W2; outh = g_w2T; R = INT_DIM; Cc = D_MODEL;
    }

    const int nTx = Cc >> 5;                 // tiles along columns
    const int bx = b % nTx, by = b / nTx;
    const int c0 = bx * 32, r0 = by * 64;

    // load 64 rows x 32 cols (each row = 128B coalesced)
    const int cc = tid & 31, rr0 = tid >> 5;
#pragma unroll
    for (int i = 0; i < 8; i++) {
        const int rr = rr0 + i * 8;
        t[rr][cc] = in[(size_t)(r0 + rr) * Cc + c0 + cc];
    }
    __syncthreads();

    // write 32 output rows x 64 cols, pairs -> 128B lines
    const int j = tid & 31, ccw = tid >> 5;
    if (outb) {
#pragma unroll
        for (int i = 0; i < 4; i++) {
            const int col = ccw + i * 8;
            *(bf162*)&outb[(size_t)(c0 + col) * R + r0 + 2 * j] =
                bf162(__float2bfloat16_rn(t[2 * j][col]),
                      __float2bfloat16_rn(t[2 * j + 1][col]));
        }
    } else {
#pragma unroll
        for (int i = 0; i < 4; i++) {
            const int col = ccw + i * 8;
            *(half2*)&outh[(size_t)(c0 + col) * R + r0 + 2 * j] =
                __halves2half2(__float2half_rn(t[2 * j][col]),
                               __float2half_rn(t[2 * j + 1][col]));
        }
    }
}

// ================= Flash attention (BLOCK_M=64, 128 thr) =====================
#define FA_STRIDE 144   /* 72 halves per row */
__global__ __launch_bounds__(128) void flash_mma()
{
    __shared__ half Qs[64 * 72];
    __shared__ half Ks[2][64 * 72];
    __shared__ half Vs[2][64 * 72];

    const int tid = threadIdx.x;
    const int lane = tid & 31, wid = tid >> 5;
    const int qb = blockIdx.x * 64;
    const int bh = blockIdx.y;
    const int mbase = wid * 16;

    const half* qp = g_qh + (size_t)bh * T_SEQ * HDIM;
    const half* kp = g_kh + (size_t)bh * T_SEQ * HDIM;
    const half* vp = g_vh + (size_t)bh * T_SEQ * HDIM;

    const uint32_t qbase = smem_u32(Qs);
    const uint32_t kbase = smem_u32(Ks);
    const uint32_t vbase = smem_u32(Vs);

#pragma unroll
    for (int t = 0; t < 8; t++) {
        int u = tid + t * 128;
        int buf = u >> 9, rem = u & 511;
        int row = rem >> 3, c = rem & 7;
        Vs[buf][row * 72 + 64 + c] = (c == 0) ? __float2half(1.0f) : __float2half(0.0f);
    }

#pragma unroll
    for (int t = 0; t < 4; t++) {
        int u = tid + t * 128;
        int row = u >> 3, j = u & 7;
        cp16(qbase + row * FA_STRIDE + j * 16, qp + (size_t)(qb + row) * 64 + j * 8);
        cp16(kbase + row * FA_STRIDE + j * 16, kp + (size_t)row * 64 + j * 8);
        cp16(vbase + row * FA_STRIDE + j * 16, vp + (size_t)row * 64 + j * 8);
    }
    CP_COMMIT();

    const int r = lane & 7;
    const int aRow = r + ((lane >> 3) & 1) * 8;
    const int aK16 = ((lane >> 4) & 1) * 16;
    const int bRow = r + ((lane >> 4) & 1) * 8;
    const int bK16 = ((lane >> 3) & 1) * 16;
    const int vRow = lane & 15;
    const int vCol = ((lane >> 4) & 1) * 8;

    float oacc[9][4];
#pragma unroll
    for (int i = 0; i < 9; i++)
#pragma unroll
        for (int j = 0; j < 4; j++) oacc[i][j] = 0.f;

    uint32_t qf[4][4];
    bool qloaded = false;
    const float CEXP = 0.1803368801f;   // log2(e)/8

    const int NIT = T_SEQ / 64;
    for (int it = 0; it < NIT; it++) {
        const int buf = it & 1;
        if (it + 1 < NIT) {
            const int nb = (it + 1) & 1;
            const half* kq = kp + (size_t)(it + 1) * 64 * 64;
            const half* vq = vp + (size_t)(it + 1) * 64 * 64;
#pragma unroll
            for (int t = 0; t < 4; t++) {
                int u = tid + t * 128;
                int row = u >> 3, j = u & 7;
                cp16(kbase + nb * 9216 + row * FA_STRIDE + j * 16, kq + (size_t)row * 64 + j * 8);
                cp16(vbase + nb * 9216 + row * FA_STRIDE + j * 16, vq + (size_t)row * 64 + j * 8);
            }
            CP_COMMIT();
            CP_WAITN(1);
        } else {
            CP_WAITN(0);
        }
        __syncthreads();

        if (!qloaded) {
            const uint32_t qa = qbase + (mbase + aRow) * FA_STRIDE + aK16;
#pragma unroll
            for (int ks = 0; ks < 4; ks++) LDM_X4(qf[ks], qa + ks * 32);
            qloaded = true;
        }

        float sacc[8][4];
#pragma unroll
        for (int i = 0; i < 8; i++)
#pragma unroll
            for (int j = 0; j < 4; j++) sacc[i][j] = 0.f;

        const uint32_t ka = kbase + buf * 9216 + bRow * FA_STRIDE + bK16;
#pragma unroll
        for (int ks = 0; ks < 4; ks++) {
            uint32_t kf[4][4];
#pragma unroll
            for (int p = 0; p < 4; p++) LDM_X4(kf[p], ka + p * 16 * FA_STRIDE + ks * 32);
#pragma unroll
            for (int nf = 0; nf < 8; nf++) {
                const int p = nf >> 1, q = (nf & 1) * 2;
                MMA_F16(sacc[nf], qf[ks], kf[p][q], kf[p][q + 1]);
            }
        }

        uint32_t pf[4][4];
#pragma unroll
        for (int t = 0; t < 4; t++) {
#pragma unroll
            for (int u = 0; u < 2; u++) {
                const int j = 2 * t + u;
                pf[t][u * 2 + 0] = exp2_f16x2(sacc[j][0] * CEXP, sacc[j][1] * CEXP);
                pf[t][u * 2 + 1] = exp2_f16x2(sacc[j][2] * CEXP, sacc[j][3] * CEXP);
            }
        }

        const uint32_t va = vbase + buf * 9216;
#pragma unroll
        for (int t = 0; t < 4; t++) {
            const uint32_t vrow = va + (t * 16 + vRow) * FA_STRIDE;
            uint32_t vf[4][4], vf8[2];
#pragma unroll
            for (int p = 0; p < 4; p++) LDM_X4T(vf[p], vrow + (p * 16 + vCol) * 2);
            LDM_X2T(vf8, vrow + 64 * 2);
#pragma unroll
            for (int nf = 0; nf < 8; nf++) {
                const int p = nf >> 1, q = (nf & 1) * 2;
                MMA_F16(oacc[nf], pf[t], vf[p][q], vf[p][q + 1]);
            }
            MMA_F16(oacc[8], pf[t], vf8[0], vf8[1]);
        }
        __syncthreads();
    }

    const int gid = lane >> 2, tg = lane & 3;
    const float l0 = __shfl_sync(0xffffffffu, oacc[8][0], lane & ~3);
    const float l1 = __shfl_sync(0xffffffffu, oacc[8][2], lane & ~3);
    const float inv0 = 1.f / l0, inv1 = 1.f / l1;

    const int b = bh >> 4, h = bh & 15;
    const size_t row0 = (size_t)(b * T_SEQ + qb + mbase + gid);
#pragma unroll
    for (int nf = 0; nf < 8; nf++) {
        const int col = h * 64 + nf * 8 + tg * 2;
        *(bf162*)&g_atb[row0 * D_MODEL + col] =
            bf162(__float2bfloat16_rn(oacc[nf][0] * inv0),
                  __float2bfloat16_rn(oacc[nf][1] * inv0));
        *(bf162*)&g_atb[(row0 + 8) * D_MODEL + col] =
            bf162(__float2bfloat16_rn(oacc[nf][2] * inv1),
                  __float2bfloat16_rn(oacc[nf][3] * inv1));
    }
}

// ================= residual + LayerNorm (optional fp16 copy) =================
template<int HOUT>
__global__ __launch_bounds__(256) void ln_kernel(
    const float* __restrict__ A, const float* __restrict__ Cv,
    const float* __restrict__ gamma, const float* __restrict__ beta,
    float* __restrict__ out, half* __restrict__ outh)
{
    __shared__ float red[18];
    const int row = blockIdx.x;
    const int tid = threadIdx.x;
    const int lane = tid & 31, wid = tid >> 5;

    float4 av = ((const float4*)(A  + (size_t)row * D_MODEL))[tid];
    float4 cv = ((const float4*)(Cv + (size_t)row * D_MODEL))[tid];
    float4 s = make_float4(av.x + cv.x, av.y + cv.y, av.z + cv.z, av.w + cv.w);

    float sum = s.x + s.y + s.z + s.w;
    float sq  = s.x * s.x + s.y * s.y + s.z * s.z + s.w * s.w;
#pragma unroll
    for (int off = 16; off; off >>= 1) {
        sum += __shfl_xor_sync(0xffffffffu, sum, off);
        sq  += __shfl_xor_sync(0xffffffffu, sq, off);
    }
    if (lane == 0) { red[wid] = sum; red[wid + 8] = sq; }
    __syncthreads();
    if (tid == 0) {
        float ts = 0.f, tq = 0.f;
        for (int i = 0; i < 8; i++) { ts += red[i]; tq += red[i + 8]; }
        red[16] = ts; red[17] = tq;
    }
    __syncthreads();

    float mean = red[16] * (1.f / 1024.f);
    float var  = red[17] * (1.f / 1024.f) - mean * mean;
    float rstd = rsqrtf(var + 1e-5f);

    float4 g4 = ((const float4*)gamma)[tid];
    float4 b4 = ((const float4*)beta)[tid];
    float4 rr;
    rr.x = (s.x - mean) * rstd * g4.x + b4.x;
    rr.y = (s.y - mean) * rstd * g4.y + b4.y;
    rr.z = (s.z - mean) * rstd * g4.z + b4.z;
    rr.w = (s.w - mean) * rstd * g4.w + b4.w;
    ((float4*)(out + (size_t)row * D_MODEL))[tid] = rr;

    if (HOUT) {
        size_t base = (size_t)row * D_MODEL + tid * 4;
        *(half2*)&outh[base]     = __floats2half2_rn(rr.x, rr.y);
        *(half2*)&outh[base + 2] = __floats2half2_rn(rr.z, rr.w);
    }
}

// ================= launch =================
extern "C" void kernel_launch(void* const* d_in, const int* in_sizes, int n_in,
                              void* d_out, int out_size)
{
    const float* x     = (const float*)d_in[0];
    const float* Wq    = (const float*)d_in[1];
    const float* bq    = (const float*)d_in[2];
    const float* Wk    = (const float*)d_in[3];
    const float* bk    = (const float*)d_in[4];
    const float* Wv    = (const float*)d_in[5];
    const float* bv    = (const float*)d_in[6];
    const float* Wo    = (const float*)d_in[7];
    const float* bo    = (const float*)d_in[8];
    const float* ln1_g = (const float*)d_in[9];
    const float* ln1_b = (const float*)d_in[10];
    const float* ln2_g = (const float*)d_in[11];
    const float* ln2_b = (const float*)d_in[12];
    const float* W1    = (const float*)d_in[13];
    const float* b1    = (const float*)d_in[14];
    const float* W2    = (const float*)d_in[15];
    const float* b2    = (const float*)d_in[16];

    float *tmp, *h;
    half *qh, *kh, *vh, *hh, *ffh, *w1T, *w2T;
    bf16 *xb, *atb, *wqkvT, *woT;
    cudaGetSymbolAddress((void**)&tmp,   g_tmp);
    cudaGetSymbolAddress((void**)&h,     g_h);
    cudaGetSymbolAddress((void**)&qh,    g_qh);
    cudaGetSymbolAddress((void**)&kh,    g_kh);
    cudaGetSymbolAddress((void**)&vh,    g_vh);
    cudaGetSymbolAddress((void**)&xb,    g_xb);
    cudaGetSymbolAddress((void**)&atb,   g_atb);
    cudaGetSymbolAddress((void**)&hh,    g_hh);
    cudaGetSymbolAddress((void**)&ffh,   g_ffh);
    cudaGetSymbolAddress((void**)&wqkvT, g_wqkvT);
    cudaGetSymbolAddress((void**)&woT,   g_woT);
    cudaGetSymbolAddress((void**)&w1T,   g_w1T);
    cudaGetSymbolAddress((void**)&w2T,   g_w2T);

    cudaFuncSetAttribute((const void*)gemm16<0, 0, bf16>, cudaFuncAttributeMaxDynamicSharedMemorySize, SMEM_G);
    cudaFuncSetAttribute((const void*)gemm16<1, 0, half>, cudaFuncAttributeMaxDynamicSharedMemorySize, SMEM_G);
    cudaFuncSetAttribute((const void*)gemm16<1, 1, half>, cudaFuncAttributeMaxDynamicSharedMemorySize, SMEM_G);
    cudaFuncSetAttribute((const void*)gemm_qkv, cudaFuncAttributeMaxDynamicSharedMemorySize, SMEM_G);

    dim3 blk256(256);
    dim3 blk128(128);

    // single fused pre-pass (coalesced)
    prep_kernel<<<PREP_BLOCKS, blk256>>>(x, Wq, Wk, Wv, Wo, W1, W2);

    dim3 gD(D_MODEL/128, M_TOT/128);       // (8, 32)
    dim3 gQKV(3*D_MODEL/128, M_TOT/128);   // (24, 32)
    dim3 gF(INT_DIM/128, M_TOT/128);       // (32, 32)

    // fused Q/K/V projection (bf16) -> fp16 [B,H,T,64]
    gemm_qkv<<<gQKV, blk256, SMEM_G>>>(xb, wqkvT, bq, bk, bv, qh, kh, vh, M_TOT, D_MODEL);

    // attention (fp16 HMMA, 64-query tiles, 128 threads) -> atb bf16 [B,T,D]
    flash_mma<<<dim3(T_SEQ/64, BATCH*NHEAD), blk128>>>();

    // output projection (bf16) -> tmp fp32
    gemm16<0, 0, bf16><<<gD, blk256, SMEM_G>>>(atb, woT, bo, tmp, nullptr, M_TOT, D_MODEL, D_MODEL);

    // h = LN(x + attn_out), fp16 copy for FFN
    ln_kernel<1><<<M_TOT, blk256>>>(x, tmp, ln1_g, ln1_b, h, hh);

    // FFN: plain fp16, f32 accum
    gemm16<1, 1, half><<<gF, blk256, SMEM_G>>>(hh, w1T, b1, nullptr, ffh, M_TOT, INT_DIM, D_MODEL);
    gemm16<1, 0, half><<<gD, blk256, SMEM_G>>>(ffh, w2T, b2, tmp, nullptr, M_TOT, D_MODEL, INT_DIM);

    // out = LN(h + ffn_out)
    ln_kernel<0><<<M_TOT, blk256>>>(h, tmp, ln2_g, ln2_b, (float*)d_out, nullptr);
}